// round 3
// baseline (speedup 1.0000x reference)
#include <cuda_runtime.h>

// Problem constants
#define B_ 2
#define T_ 2048
#define C_ 2048
#define H_ 16
#define KV_ 4
#define D_ 128
#define LP_ 64
#define L_ (T_ - LP_)
#define GROUPS_ (H_ / KV_)
#define SCALE_ 0.08838834764831845f   // 128^-0.5

// Scratch (device globals: no runtime allocation allowed)
__device__ float g_q[(size_t)B_ * T_ * H_ * D_];    // [B,T,H,D]
__device__ float g_k[(size_t)B_ * T_ * KV_ * D_];   // [B,T,KV,D]
__device__ float g_v[(size_t)B_ * T_ * KV_ * D_];   // [B,T,KV,D]
__device__ float g_ao[(size_t)B_ * T_ * H_ * D_];   // [B,T,H*D]

// ---------------------------------------------------------------------------
// SGEMM: C[M,N] = A[M,K] @ B[K,N] (+ bias[N]).  Row-major. M%128==0, N%128==0,
// K%16==0 (true for all calls here).  128x128x16 tile, 8x8 per thread.
// ---------------------------------------------------------------------------
__global__ __launch_bounds__(256) void sgemm_bias(
    int M, int N, int K,
    const float* __restrict__ A, const float* __restrict__ Bm,
    const float* __restrict__ bias, float* __restrict__ C)
{
    const int BK = 16;
    __shared__ float As[16][128 + 4];
    __shared__ float Bs[16][128 + 4];

    int tid = threadIdx.x;
    int tx = tid & 15;
    int ty = tid >> 4;
    int row0 = blockIdx.y * 128;
    int col0 = blockIdx.x * 128;

    float acc[8][8];
#pragma unroll
    for (int i = 0; i < 8; i++)
#pragma unroll
        for (int j = 0; j < 8; j++) acc[i][j] = 0.f;

    for (int k0 = 0; k0 < K; k0 += BK) {
        // Load A tile (128x16), store transposed into As[k][m]
#pragma unroll
        for (int i = 0; i < 2; i++) {
            int idx = tid + i * 256;          // 0..511  (512 float4)
            int r = idx >> 2;                 // 0..127
            int kk = (idx & 3) << 2;          // 0,4,8,12
            float4 va = *(const float4*)(A + (size_t)(row0 + r) * K + k0 + kk);
            As[kk + 0][r] = va.x;
            As[kk + 1][r] = va.y;
            As[kk + 2][r] = va.z;
            As[kk + 3][r] = va.w;
        }
        // Load B tile (16x128)
#pragma unroll
        for (int i = 0; i < 2; i++) {
            int idx = tid + i * 256;
            int kk = idx >> 5;                // 0..15
            int c = (idx & 31) << 2;          // 0..124
            *(float4*)&Bs[kk][c] = *(const float4*)(Bm + (size_t)(k0 + kk) * N + col0 + c);
        }
        __syncthreads();

#pragma unroll
        for (int kk = 0; kk < BK; kk++) {
            float ra[8], rb[8];
            *(float4*)&ra[0] = *(float4*)&As[kk][ty * 8];
            *(float4*)&ra[4] = *(float4*)&As[kk][ty * 8 + 4];
            *(float4*)&rb[0] = *(float4*)&Bs[kk][tx * 8];
            *(float4*)&rb[4] = *(float4*)&Bs[kk][tx * 8 + 4];
#pragma unroll
            for (int i = 0; i < 8; i++)
#pragma unroll
                for (int j = 0; j < 8; j++)
                    acc[i][j] += ra[i] * rb[j];
        }
        __syncthreads();
    }

#pragma unroll
    for (int i = 0; i < 8; i++) {
        int r = row0 + ty * 8 + i;
#pragma unroll
        for (int j = 0; j < 8; j += 4) {
            int c = col0 + tx * 8 + j;
            float4 vv;
            vv.x = acc[i][j + 0];
            vv.y = acc[i][j + 1];
            vv.z = acc[i][j + 2];
            vv.w = acc[i][j + 3];
            if (bias) {
                vv.x += bias[c + 0];
                vv.y += bias[c + 1];
                vv.z += bias[c + 2];
                vv.w += bias[c + 3];
            }
            *(float4*)(C + (size_t)r * N + c) = vv;
        }
    }
}

// ---------------------------------------------------------------------------
// RoPE (in place) on x laid out [B,T,NH,D]; rotates positions t>=LP using
// cos/sin of shape [B, L, D].  One thread per (b, t-LP, h, d<64) pair.
// ---------------------------------------------------------------------------
__global__ void rope_kernel(float* __restrict__ x,
                            const float* __restrict__ cs,
                            const float* __restrict__ sn, int NH)
{
    int idx = blockIdx.x * blockDim.x + threadIdx.x;
    int total = B_ * L_ * NH * 64;
    if (idx >= total) return;
    int d = idx & 63;
    int h = (idx >> 6) % NH;
    int tt = (idx / (64 * NH)) % L_;
    int b = idx / (64 * NH * L_);

    size_t base = (((size_t)b * T_ + LP_ + tt) * NH + h) * D_;
    size_t cb = ((size_t)b * L_ + tt) * D_;
    float x0 = x[base + d], x1 = x[base + d + 64];
    float c0 = cs[cb + d], c1 = cs[cb + d + 64];
    float s0 = sn[cb + d], s1 = sn[cb + d + 64];
    // out[d]      = x[d]*c[d]      - x[d+64]*s[d]
    // out[d+64]   = x[d+64]*c[d+64] + x[d]*s[d+64]
    x[base + d] = x0 * c0 - x1 * s0;
    x[base + d + 64] = x1 * c1 + x0 * s1;
}

// ---------------------------------------------------------------------------
// Flash attention, fp32, BQ=64 queries x BKV=64 keys per step, D=128.
// The reference "mask" is an additive {0,1} bias (NOT -inf), so every key
// position participates in softmax; we stream all T keys.
// Q,K tiles are stored transposed ([d][r]) with an XOR swizzle on 4-float
// column groups so the S-phase float4 reads are conflict-free.
// smem: Qs 32KB + Ks 32KB + Vs 32KB + Ps 16KB = 112KB (dynamic).
// ---------------------------------------------------------------------------
#define BQ 64
#define BKV 64

__global__ __launch_bounds__(256) void flash_kernel(
    const float* __restrict__ q, const float* __restrict__ k,
    const float* __restrict__ v, float* __restrict__ o)
{
    extern __shared__ float sm[];
    float* Qs = sm;                   // [128][64] transposed+swizzled
    float* Ks = Qs + 128 * 64;        // [128][64] transposed+swizzled
    float* Vs = Ks + 128 * 64;        // [64][128]
    float* Ps = Vs + 64 * 128;        // [64][64]

    int tid = threadIdx.x;
    int tx = tid & 15;       // S-col group (4 cols)
    int ty = tid >> 4;       // S-row group (4 rows)
    int bh = blockIdx.y;
    int b = bh / H_, h = bh % H_;
    int kvh = h / GROUPS_;
    int q0 = blockIdx.x * BQ;

    // ---- load Q tile, transposed + swizzled ----
    for (int i = tid; i < BQ * D_ / 4; i += 256) {
        int r = i >> 5;               // row 0..63 (32 float4 per row)
        int d4 = (i & 31) << 2;
        float4 vq = *(const float4*)(q + ((((size_t)b * T_ + q0 + r) * H_ + h) * D_ + d4));
        float tmp[4] = {vq.x, vq.y, vq.z, vq.w};
#pragma unroll
        for (int u = 0; u < 4; u++) {
            int d = d4 + u;
            int c4 = (r >> 2) ^ ((d >> 2) & 15);
            Qs[d * 64 + (c4 << 2) + (r & 3)] = tmp[u];
        }
    }

    float m[4], l[4], acc[4][8];
#pragma unroll
    for (int i = 0; i < 4; i++) {
        m[i] = -1e30f;
        l[i] = 0.f;
#pragma unroll
        for (int j = 0; j < 8; j++) acc[i][j] = 0.f;
    }

    for (int kv0 = 0; kv0 < T_; kv0 += BKV) {
        // ---- load K (transposed+swizzled) and V (row-major) ----
        for (int i = tid; i < BKV * D_ / 4; i += 256) {
            int r = i >> 5;
            int d4 = (i & 31) << 2;
            size_t gofs = (((size_t)b * T_ + kv0 + r) * KV_ + kvh) * D_ + d4;
            float4 vk = *(const float4*)(k + gofs);
            float tmpk[4] = {vk.x, vk.y, vk.z, vk.w};
#pragma unroll
            for (int u = 0; u < 4; u++) {
                int d = d4 + u;
                int c4 = (r >> 2) ^ ((d >> 2) & 15);
                Ks[d * 64 + (c4 << 2) + (r & 3)] = tmpk[u];
            }
            *(float4*)&Vs[r * D_ + d4] = *(const float4*)(v + gofs);
        }
        __syncthreads();   // also covers Q tile on first iteration

        // ---- S = Q @ K^T (4x4 per thread) ----
        float s[4][4];
#pragma unroll
        for (int i = 0; i < 4; i++)
#pragma unroll
            for (int j = 0; j < 4; j++) s[i][j] = 0.f;

#pragma unroll 4
        for (int d = 0; d < D_; d++) {
            int swz = (d >> 2) & 15;
            float4 kj = *(const float4*)&Ks[d * 64 + ((tx ^ swz) << 2)];
            float4 qi = *(const float4*)&Qs[d * 64 + ((ty ^ swz) << 2)];
            s[0][0] += qi.x * kj.x; s[0][1] += qi.x * kj.y; s[0][2] += qi.x * kj.z; s[0][3] += qi.x * kj.w;
            s[1][0] += qi.y * kj.x; s[1][1] += qi.y * kj.y; s[1][2] += qi.y * kj.z; s[1][3] += qi.y * kj.w;
            s[2][0] += qi.z * kj.x; s[2][1] += qi.z * kj.y; s[2][2] += qi.z * kj.z; s[2][3] += qi.z * kj.w;
            s[3][0] += qi.w * kj.x; s[3][1] += qi.w * kj.y; s[3][2] += qi.w * kj.z; s[3][3] += qi.w * kj.w;
        }

        // ---- scale + additive {0,1} bias, online softmax ----
#pragma unroll
        for (int i = 0; i < 4; i++) {
            int ig = q0 + ty * 4 + i;
#pragma unroll
            for (int j = 0; j < 4; j++) {
                int jg = kv0 + tx * 4 + j;
                float bias = ((jg < LP_) || (ig >= LP_ && jg <= ig)) ? 1.0f : 0.0f;
                s[i][j] = s[i][j] * SCALE_ + bias;
            }
        }

#pragma unroll
        for (int i = 0; i < 4; i++) {
            float mx = fmaxf(fmaxf(s[i][0], s[i][1]), fmaxf(s[i][2], s[i][3]));
#pragma unroll
            for (int off = 8; off; off >>= 1)
                mx = fmaxf(mx, __shfl_xor_sync(0xffffffffu, mx, off));
            float mnew = fmaxf(m[i], mx);
            float alpha = __expf(m[i] - mnew);
            float psum = 0.f;
#pragma unroll
            for (int j = 0; j < 4; j++) {
                float p = __expf(s[i][j] - mnew);
                s[i][j] = p;
                psum += p;
            }
#pragma unroll
            for (int off = 8; off; off >>= 1)
                psum += __shfl_xor_sync(0xffffffffu, psum, off);
            l[i] = l[i] * alpha + psum;
            m[i] = mnew;
#pragma unroll
            for (int j = 0; j < 8; j++) acc[i][j] *= alpha;
            *(float4*)&Ps[(ty * 4 + i) * 64 + tx * 4] =
                make_float4(s[i][0], s[i][1], s[i][2], s[i][3]);
        }
        __syncthreads();

        // ---- O += P @ V  (thread owns cols tx*4..+3 and 64+tx*4..+3) ----
        for (int j0 = 0; j0 < BKV; j0 += 4) {
            float pr[4][4];
#pragma unroll
            for (int i = 0; i < 4; i++)
                *(float4*)pr[i] = *(float4*)&Ps[(ty * 4 + i) * 64 + j0];
#pragma unroll
            for (int jj = 0; jj < 4; jj++) {
                float4 vlo = *(const float4*)&Vs[(j0 + jj) * D_ + tx * 4];
                float4 vhi = *(const float4*)&Vs[(j0 + jj) * D_ + 64 + tx * 4];
#pragma unroll
                for (int i = 0; i < 4; i++) {
                    float p = pr[i][jj];
                    acc[i][0] += p * vlo.x; acc[i][1] += p * vlo.y;
                    acc[i][2] += p * vlo.z; acc[i][3] += p * vlo.w;
                    acc[i][4] += p * vhi.x; acc[i][5] += p * vhi.y;
                    acc[i][6] += p * vhi.z; acc[i][7] += p * vhi.w;
                }
            }
        }
        __syncthreads();
    }

    // ---- normalize + write [B,T,H*D] ----
#pragma unroll
    for (int i = 0; i < 4; i++) {
        float inv = 1.0f / l[i];
        int r = q0 + ty * 4 + i;
        size_t base = (((size_t)b * T_ + r) * H_ + h) * D_;
        float4 o0 = make_float4(acc[i][0] * inv, acc[i][1] * inv,
                                acc[i][2] * inv, acc[i][3] * inv);
        float4 o1 = make_float4(acc[i][4] * inv, acc[i][5] * inv,
                                acc[i][6] * inv, acc[i][7] * inv);
        *(float4*)(o + base + tx * 4) = o0;
        *(float4*)(o + base + 64 + tx * 4) = o1;
    }
}

// ---------------------------------------------------------------------------
extern "C" void kernel_launch(void* const* d_in, const int* in_sizes, int n_in,
                              void* d_out, int out_size)
{
    const float* hs = (const float*)d_in[0];   // hidden_states [B,T,C]
    const float* cs = (const float*)d_in[1];   // cos [B,L,D]
    const float* sn = (const float*)d_in[2];   // sin [B,L,D]
    const float* Wq = (const float*)d_in[3];   // [C, H*D]
    const float* bq = (const float*)d_in[4];
    const float* Wk = (const float*)d_in[5];   // [C, KV*D]
    const float* bk = (const float*)d_in[6];
    const float* Wv = (const float*)d_in[7];
    const float* bv = (const float*)d_in[8];
    const float* Wo = (const float*)d_in[9];   // [H*D, C]
    float* out = (float*)d_out;

    float *qp, *kp, *vp, *aop;
    cudaGetSymbolAddress((void**)&qp, g_q);
    cudaGetSymbolAddress((void**)&kp, g_k);
    cudaGetSymbolAddress((void**)&vp, g_v);
    cudaGetSymbolAddress((void**)&aop, g_ao);

    const size_t shmem = (size_t)(128 * 64 * 2 + 64 * 128 + 64 * 64) * sizeof(float); // 114688
    cudaFuncSetAttribute(flash_kernel, cudaFuncAttributeMaxDynamicSharedMemorySize,
                         (int)shmem);

    const int M = B_ * T_;

    // QKV projections
    sgemm_bias<<<dim3((H_ * D_) / 128, M / 128), 256>>>(M, H_ * D_, C_, hs, Wq, bq, qp);
    sgemm_bias<<<dim3((KV_ * D_) / 128, M / 128), 256>>>(M, KV_ * D_, C_, hs, Wk, bk, kp);
    sgemm_bias<<<dim3((KV_ * D_) / 128, M / 128), 256>>>(M, KV_ * D_, C_, hs, Wv, bv, vp);

    // RoPE (q and k, positions >= LP)
    {
        int totq = B_ * L_ * H_ * 64;
        rope_kernel<<<(totq + 255) / 256, 256>>>(qp, cs, sn, H_);
        int totk = B_ * L_ * KV_ * 64;
        rope_kernel<<<(totk + 255) / 256, 256>>>(kp, cs, sn, KV_);
    }

    // Attention
    flash_kernel<<<dim3(T_ / BQ, B_ * H_), 256, shmem>>>(qp, kp, vp, aop);

    // Output projection
    sgemm_bias<<<dim3(C_ / 128, M / 128), 256>>>(M, C_, H_ * D_, aop, Wo, nullptr, out);
}

// round 5
// speedup vs baseline: 1.0008x; 1.0008x over previous
#include <cuda_runtime.h>

// Problem constants
#define B_ 2
#define T_ 2048
#define C_ 2048
#define H_ 16
#define KV_ 4
#define D_ 128
#define LP_ 64
#define L_ (T_ - LP_)
#define GROUPS_ (H_ / KV_)
#define SCALE_ 0.08838834764831845f   // 128^-0.5

// Scratch (device globals: no runtime allocation allowed)
__device__ float g_q[(size_t)B_ * T_ * H_ * D_];    // [B,T,H,D]
__device__ float g_k[(size_t)B_ * T_ * KV_ * D_];   // [B,T,KV,D]
__device__ float g_v[(size_t)B_ * T_ * KV_ * D_];   // [B,T,KV,D]
__device__ float g_ao[(size_t)B_ * T_ * H_ * D_];   // [B,T,H*D]

// ---------------------------------------------------------------------------
// SGEMM: C[M,N] = A[M,K] @ B[K,N] (+ bias[N]).  Row-major. M%128==0, N%128==0,
// K%16==0 (true for all calls here).  128x128x16 tile, 8x8 per thread.
// ---------------------------------------------------------------------------
__global__ __launch_bounds__(256) void sgemm_bias(
    int M, int N, int K,
    const float* __restrict__ A, const float* __restrict__ Bm,
    const float* __restrict__ bias, float* __restrict__ C)
{
    const int BK = 16;
    __shared__ float As[16][128 + 4];
    __shared__ float Bs[16][128 + 4];

    int tid = threadIdx.x;
    int tx = tid & 15;
    int ty = tid >> 4;
    int row0 = blockIdx.y * 128;
    int col0 = blockIdx.x * 128;

    float acc[8][8];
#pragma unroll
    for (int i = 0; i < 8; i++)
#pragma unroll
        for (int j = 0; j < 8; j++) acc[i][j] = 0.f;

    for (int k0 = 0; k0 < K; k0 += BK) {
        // Load A tile (128x16), store transposed into As[k][m]
#pragma unroll
        for (int i = 0; i < 2; i++) {
            int idx = tid + i * 256;          // 0..511  (512 float4)
            int r = idx >> 2;                 // 0..127
            int kk = (idx & 3) << 2;          // 0,4,8,12
            float4 va = *(const float4*)(A + (size_t)(row0 + r) * K + k0 + kk);
            As[kk + 0][r] = va.x;
            As[kk + 1][r] = va.y;
            As[kk + 2][r] = va.z;
            As[kk + 3][r] = va.w;
        }
        // Load B tile (16x128)
#pragma unroll
        for (int i = 0; i < 2; i++) {
            int idx = tid + i * 256;
            int kk = idx >> 5;                // 0..15
            int c = (idx & 31) << 2;          // 0..124
            *(float4*)&Bs[kk][c] = *(const float4*)(Bm + (size_t)(k0 + kk) * N + col0 + c);
        }
        __syncthreads();

#pragma unroll
        for (int kk = 0; kk < BK; kk++) {
            float ra[8], rb[8];
            *(float4*)&ra[0] = *(float4*)&As[kk][ty * 8];
            *(float4*)&ra[4] = *(float4*)&As[kk][ty * 8 + 4];
            *(float4*)&rb[0] = *(float4*)&Bs[kk][tx * 8];
            *(float4*)&rb[4] = *(float4*)&Bs[kk][tx * 8 + 4];
#pragma unroll
            for (int i = 0; i < 8; i++)
#pragma unroll
                for (int j = 0; j < 8; j++)
                    acc[i][j] += ra[i] * rb[j];
        }
        __syncthreads();
    }

#pragma unroll
    for (int i = 0; i < 8; i++) {
        int r = row0 + ty * 8 + i;
#pragma unroll
        for (int j = 0; j < 8; j += 4) {
            int c = col0 + tx * 8 + j;
            float4 vv;
            vv.x = acc[i][j + 0];
            vv.y = acc[i][j + 1];
            vv.z = acc[i][j + 2];
            vv.w = acc[i][j + 3];
            if (bias) {
                vv.x += bias[c + 0];
                vv.y += bias[c + 1];
                vv.z += bias[c + 2];
                vv.w += bias[c + 3];
            }
            *(float4*)(C + (size_t)r * N + c) = vv;
        }
    }
}

// ---------------------------------------------------------------------------
// RoPE (in place) on x laid out [B,T,NH,D]; rotates positions t>=LP using
// cos/sin of shape [B, L, D].  One thread per (b, t-LP, h, d<64) pair.
// ---------------------------------------------------------------------------
__global__ void rope_kernel(float* __restrict__ x,
                            const float* __restrict__ cs,
                            const float* __restrict__ sn, int NH)
{
    int idx = blockIdx.x * blockDim.x + threadIdx.x;
    int total = B_ * L_ * NH * 64;
    if (idx >= total) return;
    int d = idx & 63;
    int h = (idx >> 6) % NH;
    int tt = (idx / (64 * NH)) % L_;
    int b = idx / (64 * NH * L_);

    size_t base = (((size_t)b * T_ + LP_ + tt) * NH + h) * D_;
    size_t cb = ((size_t)b * L_ + tt) * D_;
    float x0 = x[base + d], x1 = x[base + d + 64];
    float c0 = cs[cb + d], c1 = cs[cb + d + 64];
    float s0 = sn[cb + d], s1 = sn[cb + d + 64];
    // out[d]      = x[d]*c[d]      - x[d+64]*s[d]
    // out[d+64]   = x[d+64]*c[d+64] + x[d]*s[d+64]
    x[base + d] = x0 * c0 - x1 * s0;
    x[base + d + 64] = x1 * c1 + x0 * s1;
}

// ---------------------------------------------------------------------------
// Flash attention, fp32, BQ=64 queries x BKV=64 keys per step, D=128.
// The reference "mask" is an additive {0,1} bias (NOT -inf), so every key
// position participates in softmax; we stream all T keys.
// Q,K tiles are stored transposed ([d][r]) with an XOR swizzle on 4-float
// column groups so the S-phase float4 reads are conflict-free.
// smem: Qs 32KB + Ks 32KB + Vs 32KB + Ps 16KB = 112KB (dynamic).
// ---------------------------------------------------------------------------
#define BQ 64
#define BKV 64

__global__ __launch_bounds__(256) void flash_kernel(
    const float* __restrict__ q, const float* __restrict__ k,
    const float* __restrict__ v, float* __restrict__ o)
{
    extern __shared__ float sm[];
    float* Qs = sm;                   // [128][64] transposed+swizzled
    float* Ks = Qs + 128 * 64;        // [128][64] transposed+swizzled
    float* Vs = Ks + 128 * 64;        // [64][128]
    float* Ps = Vs + 64 * 128;        // [64][64]

    int tid = threadIdx.x;
    int tx = tid & 15;       // S-col group (4 cols)
    int ty = tid >> 4;       // S-row group (4 rows)
    int bh = blockIdx.y;
    int b = bh / H_, h = bh % H_;
    int kvh = h / GROUPS_;
    int q0 = blockIdx.x * BQ;

    // ---- load Q tile, transposed + swizzled ----
    for (int i = tid; i < BQ * D_ / 4; i += 256) {
        int r = i >> 5;               // row 0..63 (32 float4 per row)
        int d4 = (i & 31) << 2;
        float4 vq = *(const float4*)(q + ((((size_t)b * T_ + q0 + r) * H_ + h) * D_ + d4));
        float tmp[4] = {vq.x, vq.y, vq.z, vq.w};
#pragma unroll
        for (int u = 0; u < 4; u++) {
            int d = d4 + u;
            int c4 = (r >> 2) ^ ((d >> 2) & 15);
            Qs[d * 64 + (c4 << 2) + (r & 3)] = tmp[u];
        }
    }

    float m[4], l[4], acc[4][8];
#pragma unroll
    for (int i = 0; i < 4; i++) {
        m[i] = -1e30f;
        l[i] = 0.f;
#pragma unroll
        for (int j = 0; j < 8; j++) acc[i][j] = 0.f;
    }

    for (int kv0 = 0; kv0 < T_; kv0 += BKV) {
        // ---- load K (transposed+swizzled) and V (row-major) ----
        for (int i = tid; i < BKV * D_ / 4; i += 256) {
            int r = i >> 5;
            int d4 = (i & 31) << 2;
            size_t gofs = (((size_t)b * T_ + kv0 + r) * KV_ + kvh) * D_ + d4;
            float4 vk = *(const float4*)(k + gofs);
            float tmpk[4] = {vk.x, vk.y, vk.z, vk.w};
#pragma unroll
            for (int u = 0; u < 4; u++) {
                int d = d4 + u;
                int c4 = (r >> 2) ^ ((d >> 2) & 15);
                Ks[d * 64 + (c4 << 2) + (r & 3)] = tmpk[u];
            }
            *(float4*)&Vs[r * D_ + d4] = *(const float4*)(v + gofs);
        }
        __syncthreads();   // also covers Q tile on first iteration

        // ---- S = Q @ K^T (4x4 per thread) ----
        float s[4][4];
#pragma unroll
        for (int i = 0; i < 4; i++)
#pragma unroll
            for (int j = 0; j < 4; j++) s[i][j] = 0.f;

#pragma unroll 4
        for (int d = 0; d < D_; d++) {
            int swz = (d >> 2) & 15;
            float4 kj = *(const float4*)&Ks[d * 64 + ((tx ^ swz) << 2)];
            float4 qi = *(const float4*)&Qs[d * 64 + ((ty ^ swz) << 2)];
            s[0][0] += qi.x * kj.x; s[0][1] += qi.x * kj.y; s[0][2] += qi.x * kj.z; s[0][3] += qi.x * kj.w;
            s[1][0] += qi.y * kj.x; s[1][1] += qi.y * kj.y; s[1][2] += qi.y * kj.z; s[1][3] += qi.y * kj.w;
            s[2][0] += qi.z * kj.x; s[2][1] += qi.z * kj.y; s[2][2] += qi.z * kj.z; s[2][3] += qi.z * kj.w;
            s[3][0] += qi.w * kj.x; s[3][1] += qi.w * kj.y; s[3][2] += qi.w * kj.z; s[3][3] += qi.w * kj.w;
        }

        // ---- scale + additive {0,1} bias, online softmax ----
#pragma unroll
        for (int i = 0; i < 4; i++) {
            int ig = q0 + ty * 4 + i;
#pragma unroll
            for (int j = 0; j < 4; j++) {
                int jg = kv0 + tx * 4 + j;
                float bias = ((jg < LP_) || (ig >= LP_ && jg <= ig)) ? 1.0f : 0.0f;
                s[i][j] = s[i][j] * SCALE_ + bias;
            }
        }

#pragma unroll
        for (int i = 0; i < 4; i++) {
            float mx = fmaxf(fmaxf(s[i][0], s[i][1]), fmaxf(s[i][2], s[i][3]));
#pragma unroll
            for (int off = 8; off; off >>= 1)
                mx = fmaxf(mx, __shfl_xor_sync(0xffffffffu, mx, off));
            float mnew = fmaxf(m[i], mx);
            float alpha = __expf(m[i] - mnew);
            float psum = 0.f;
#pragma unroll
            for (int j = 0; j < 4; j++) {
                float p = __expf(s[i][j] - mnew);
                s[i][j] = p;
                psum += p;
            }
#pragma unroll
            for (int off = 8; off; off >>= 1)
                psum += __shfl_xor_sync(0xffffffffu, psum, off);
            l[i] = l[i] * alpha + psum;
            m[i] = mnew;
#pragma unroll
            for (int j = 0; j < 8; j++) acc[i][j] *= alpha;
            *(float4*)&Ps[(ty * 4 + i) * 64 + tx * 4] =
                make_float4(s[i][0], s[i][1], s[i][2], s[i][3]);
        }
        __syncthreads();

        // ---- O += P @ V  (thread owns cols tx*4..+3 and 64+tx*4..+3) ----
        for (int j0 = 0; j0 < BKV; j0 += 4) {
            float pr[4][4];
#pragma unroll
            for (int i = 0; i < 4; i++)
                *(float4*)pr[i] = *(float4*)&Ps[(ty * 4 + i) * 64 + j0];
#pragma unroll
            for (int jj = 0; jj < 4; jj++) {
                float4 vlo = *(const float4*)&Vs[(j0 + jj) * D_ + tx * 4];
                float4 vhi = *(const float4*)&Vs[(j0 + jj) * D_ + 64 + tx * 4];
#pragma unroll
                for (int i = 0; i < 4; i++) {
                    float p = pr[i][jj];
                    acc[i][0] += p * vlo.x; acc[i][1] += p * vlo.y;
                    acc[i][2] += p * vlo.z; acc[i][3] += p * vlo.w;
                    acc[i][4] += p * vhi.x; acc[i][5] += p * vhi.y;
                    acc[i][6] += p * vhi.z; acc[i][7] += p * vhi.w;
                }
            }
        }
        __syncthreads();
    }

    // ---- normalize + write [B,T,H*D] ----
#pragma unroll
    for (int i = 0; i < 4; i++) {
        float inv = 1.0f / l[i];
        int r = q0 + ty * 4 + i;
        size_t base = (((size_t)b * T_ + r) * H_ + h) * D_;
        float4 o0 = make_float4(acc[i][0] * inv, acc[i][1] * inv,
                                acc[i][2] * inv, acc[i][3] * inv);
        float4 o1 = make_float4(acc[i][4] * inv, acc[i][5] * inv,
                                acc[i][6] * inv, acc[i][7] * inv);
        *(float4*)(o + base + tx * 4) = o0;
        *(float4*)(o + base + 64 + tx * 4) = o1;
    }
}

// ---------------------------------------------------------------------------
extern "C" void kernel_launch(void* const* d_in, const int* in_sizes, int n_in,
                              void* d_out, int out_size)
{
    const float* hs = (const float*)d_in[0];   // hidden_states [B,T,C]
    const float* cs = (const float*)d_in[1];   // cos [B,L,D]
    const float* sn = (const float*)d_in[2];   // sin [B,L,D]
    const float* Wq = (const float*)d_in[3];   // [C, H*D]
    const float* bq = (const float*)d_in[4];
    const float* Wk = (const float*)d_in[5];   // [C, KV*D]
    const float* bk = (const float*)d_in[6];
    const float* Wv = (const float*)d_in[7];
    const float* bv = (const float*)d_in[8];
    const float* Wo = (const float*)d_in[9];   // [H*D, C]
    float* out = (float*)d_out;

    float *qp, *kp, *vp, *aop;
    cudaGetSymbolAddress((void**)&qp, g_q);
    cudaGetSymbolAddress((void**)&kp, g_k);
    cudaGetSymbolAddress((void**)&vp, g_v);
    cudaGetSymbolAddress((void**)&aop, g_ao);

    const size_t shmem = (size_t)(128 * 64 * 2 + 64 * 128 + 64 * 64) * sizeof(float); // 114688
    cudaFuncSetAttribute(flash_kernel, cudaFuncAttributeMaxDynamicSharedMemorySize,
                         (int)shmem);

    const int M = B_ * T_;

    // QKV projections
    sgemm_bias<<<dim3((H_ * D_) / 128, M / 128), 256>>>(M, H_ * D_, C_, hs, Wq, bq, qp);
    sgemm_bias<<<dim3((KV_ * D_) / 128, M / 128), 256>>>(M, KV_ * D_, C_, hs, Wk, bk, kp);
    sgemm_bias<<<dim3((KV_ * D_) / 128, M / 128), 256>>>(M, KV_ * D_, C_, hs, Wv, bv, vp);

    // RoPE (q and k, positions >= LP)
    {
        int totq = B_ * L_ * H_ * 64;
        rope_kernel<<<(totq + 255) / 256, 256>>>(qp, cs, sn, H_);
        int totk = B_ * L_ * KV_ * 64;
        rope_kernel<<<(totk + 255) / 256, 256>>>(kp, cs, sn, KV_);
    }

    // Attention
    flash_kernel<<<dim3(T_ / BQ, B_ * H_), 256, shmem>>>(qp, kp, vp, aop);

    // Output projection
    sgemm_bias<<<dim3(C_ / 128, M / 128), 256>>>(M, C_, H_ * D_, aop, Wo, nullptr, out);
}

// round 7
// speedup vs baseline: 6.0443x; 6.0397x over previous
#include <cuda_runtime.h>
#include <cuda_fp16.h>

// Problem constants
#define B_ 2
#define T_ 2048
#define C_ 2048
#define H_ 16
#define KV_ 4
#define D_ 128
#define LP_ 64
#define L_ (T_ - LP_)
#define GROUPS_ (H_ / KV_)
#define SCALE_ 0.08838834764831845f   // 128^-0.5
#define MTOT_ (B_ * T_)

// ---------------- scratch (no runtime allocation allowed) -------------------
__device__ __half g_hsh[(size_t)MTOT_ * C_];        // hidden_states fp16
__device__ __half g_wqh[(size_t)C_ * H_ * D_];
__device__ __half g_wkh[(size_t)C_ * KV_ * D_];
__device__ __half g_wvh[(size_t)C_ * KV_ * D_];
__device__ __half g_woh[(size_t)H_ * D_ * C_];
__device__ __half g_qh [(size_t)MTOT_ * H_ * D_];   // [B,T,H,D] fp16
__device__ __half g_kh [(size_t)MTOT_ * KV_ * D_];
__device__ __half g_vh [(size_t)MTOT_ * KV_ * D_];
__device__ __half g_aoh[(size_t)MTOT_ * H_ * D_];   // attention out fp16

// ---------------- PTX helpers ----------------------------------------------
__device__ __forceinline__ unsigned smem_u32(const void* p) {
    return (unsigned)__cvta_generic_to_shared(p);
}
__device__ __forceinline__ void cp16(void* dst, const void* src) {
    asm volatile("cp.async.cg.shared.global [%0], [%1], 16;"
                 :: "r"(smem_u32(dst)), "l"(src));
}
__device__ __forceinline__ void cp_commit() { asm volatile("cp.async.commit_group;"); }
__device__ __forceinline__ void cp_wait_all() { asm volatile("cp.async.wait_group 0;"); }

__device__ __forceinline__ void ldsm4(unsigned* a, unsigned addr) {
    asm volatile("ldmatrix.sync.aligned.m8n8.x4.shared.b16 {%0,%1,%2,%3}, [%4];"
                 : "=r"(a[0]), "=r"(a[1]), "=r"(a[2]), "=r"(a[3]) : "r"(addr));
}
__device__ __forceinline__ void ldsm2(unsigned* b, unsigned addr) {
    asm volatile("ldmatrix.sync.aligned.m8n8.x2.shared.b16 {%0,%1}, [%2];"
                 : "=r"(b[0]), "=r"(b[1]) : "r"(addr));
}
__device__ __forceinline__ void ldsm2t(unsigned* b, unsigned addr) {
    asm volatile("ldmatrix.sync.aligned.m8n8.x2.trans.shared.b16 {%0,%1}, [%2];"
                 : "=r"(b[0]), "=r"(b[1]) : "r"(addr));
}
__device__ __forceinline__ void mma16816(float* c, const unsigned* a, const unsigned* b) {
    asm volatile(
        "mma.sync.aligned.m16n8k16.row.col.f32.f16.f16.f32 "
        "{%0,%1,%2,%3},{%4,%5,%6,%7},{%8,%9},{%0,%1,%2,%3};"
        : "+f"(c[0]), "+f"(c[1]), "+f"(c[2]), "+f"(c[3])
        : "r"(a[0]), "r"(a[1]), "r"(a[2]), "r"(a[3]), "r"(b[0]), "r"(b[1]));
}
__device__ __forceinline__ unsigned pack_h2(float a, float b) {
    __half2 h = __floats2half2_rn(a, b);
    return *reinterpret_cast<unsigned*>(&h);
}

// ---------------- fp32 -> fp16 convert --------------------------------------
__global__ void f2h_kernel(const float* __restrict__ x, __half* __restrict__ y, int n4) {
    int i = blockIdx.x * blockDim.x + threadIdx.x;
    if (i >= n4) return;
    float4 v = ((const float4*)x)[i];
    ((__half2*)y)[i * 2 + 0] = __floats2half2_rn(v.x, v.y);
    ((__half2*)y)[i * 2 + 1] = __floats2half2_rn(v.z, v.w);
}

// ---------------- RoPE in place on half [B,T,NH,D] --------------------------
__global__ void rope_h(__half* __restrict__ x, const float* __restrict__ cs,
                       const float* __restrict__ sn, int NH) {
    int idx = blockIdx.x * blockDim.x + threadIdx.x;
    int total = B_ * L_ * NH * 64;
    if (idx >= total) return;
    int d = idx & 63;
    int h = (idx >> 6) % NH;
    int tt = (idx / (64 * NH)) % L_;
    int b = idx / (64 * NH * L_);
    size_t base = (((size_t)b * T_ + LP_ + tt) * NH + h) * D_;
    size_t cb = ((size_t)b * L_ + tt) * D_;
    float x0 = __half2float(x[base + d]), x1 = __half2float(x[base + d + 64]);
    float c0 = cs[cb + d], c1 = cs[cb + d + 64];
    float s0 = sn[cb + d], s1 = sn[cb + d + 64];
    x[base + d]      = __float2half_rn(x0 * c0 - x1 * s0);
    x[base + d + 64] = __float2half_rn(x1 * c1 + x0 * s1);
}

// ---------------- fp16 tensor-core GEMM --------------------------------------
// C[M,N] = A[M,K] @ B[K,N] (+bias). 128x128x64 tile, 8 warps (64x32 each),
// cp.async double buffer, XOR-swizzled smem, ldmatrix + mma.m16n8k16.
__device__ __forceinline__ void gemm_load_tile(
    __half* As_, __half* Bs_, const __half* __restrict__ A, const __half* __restrict__ B,
    int row0, int col0, int k0, int K, int N, int tid)
{
#pragma unroll
    for (int j = 0; j < 4; j++) {             // A: 128x64 halves = 1024 x 16B
        int idx = tid + j * 256;
        int ar = idx >> 3, ac = idx & 7;
        cp16(As_ + ar * 64 + ((ac ^ (ar & 7)) << 3),
             A + (size_t)(row0 + ar) * K + k0 + (ac << 3));
    }
#pragma unroll
    for (int j = 0; j < 4; j++) {             // B: 64x128 halves
        int idx = tid + j * 256;
        int br = idx >> 4, bc = idx & 15;
        int pc = (bc & 8) | ((bc ^ br) & 7);
        cp16(Bs_ + br * 128 + (pc << 3),
             B + (size_t)(k0 + br) * N + col0 + (bc << 3));
    }
    cp_commit();
}

template <int OUT_HALF>
__global__ __launch_bounds__(256) void hgemm(
    int M, int N, int K,
    const __half* __restrict__ A, const __half* __restrict__ B,
    const float* __restrict__ bias, void* __restrict__ Cout)
{
    extern __shared__ __half sgm[];
    const int STG = 128 * 64 + 64 * 128;      // halves per stage
    int tid = threadIdx.x;
    int wid = tid >> 5, lane = tid & 31;
    int wm = wid & 1, wn = wid >> 1;
    int row0 = blockIdx.y * 128, col0 = blockIdx.x * 128;

    float acc[4][4][4];
#pragma unroll
    for (int i = 0; i < 4; i++)
#pragma unroll
        for (int j = 0; j < 4; j++)
#pragma unroll
            for (int t = 0; t < 4; t++) acc[i][j][t] = 0.f;

    const int nIter = K / 64;
    gemm_load_tile(sgm, sgm + 128 * 64, A, B, row0, col0, 0, K, N, tid);

    for (int it = 0; it < nIter; it++) {
        cp_wait_all();
        __syncthreads();
        if (it + 1 < nIter) {
            __half* As_ = sgm + ((it + 1) & 1) * STG;
            gemm_load_tile(As_, As_ + 128 * 64, A, B, row0, col0, (it + 1) * 64, K, N, tid);
        }
        const __half* As = sgm + (it & 1) * STG;
        const __half* Bs = As + 128 * 64;
#pragma unroll
        for (int ks = 0; ks < 4; ks++) {
            unsigned af[4][4];
#pragma unroll
            for (int mt = 0; mt < 4; mt++) {
                int mm = lane >> 3;
                int r = wm * 64 + mt * 16 + ((mm & 1) << 3) + (lane & 7);
                int c = (ks << 1) + (mm >> 1);
                ldsm4(af[mt], smem_u32(As + r * 64 + (((c ^ r) & 7) << 3)));
            }
#pragma unroll
            for (int nt = 0; nt < 4; nt++) {
                unsigned bf[2];
                int kr = (ks << 4) + (lane & 15);
                int c = (wn << 2) + nt;
                int pc = (c & 8) | ((c ^ kr) & 7);
                ldsm2t(bf, smem_u32(Bs + kr * 128 + (pc << 3)));
#pragma unroll
                for (int mt = 0; mt < 4; mt++) mma16816(acc[mt][nt], af[mt], bf);
            }
        }
    }

#pragma unroll
    for (int mt = 0; mt < 4; mt++)
#pragma unroll
        for (int nt = 0; nt < 4; nt++) {
            int r = row0 + wm * 64 + mt * 16 + (lane >> 2);
            int c = col0 + (wn << 5) + (nt << 3) + ((lane & 3) << 1);
            float b0 = bias ? bias[c] : 0.f;
            float b1 = bias ? bias[c + 1] : 0.f;
            if (OUT_HALF) {
                __half* O = (__half*)Cout;
                *(__half2*)(O + (size_t)r * N + c) =
                    __floats2half2_rn(acc[mt][nt][0] + b0, acc[mt][nt][1] + b1);
                *(__half2*)(O + (size_t)(r + 8) * N + c) =
                    __floats2half2_rn(acc[mt][nt][2] + b0, acc[mt][nt][3] + b1);
            } else {
                float* O = (float*)Cout;
                *(float2*)(O + (size_t)r * N + c) =
                    make_float2(acc[mt][nt][0] + b0, acc[mt][nt][1] + b1);
                *(float2*)(O + (size_t)(r + 8) * N + c) =
                    make_float2(acc[mt][nt][2] + b0, acc[mt][nt][3] + b1);
            }
        }
}

// ---------------- fp16 flash attention ---------------------------------------
// BQ=128 (16 rows per warp), BKV=64, D=128. S = Q@K^T and O += P@V via HMMA.
// Additive {0,1} bias (not -inf): stream ALL keys, bias folded pre-softmax.
__global__ __launch_bounds__(256) void flash_h(
    const __half* __restrict__ q, const __half* __restrict__ k,
    const __half* __restrict__ v, __half* __restrict__ o)
{
    extern __shared__ __half sgm[];
    __half* Qs = sgm;                       // [128][128] swizzled
    __half* KV = sgm + 128 * 128;           // 2 stages x {K[64][128], V[64][128]}
    const int KVSTG = 2 * 64 * 128;

    int tid = threadIdx.x;
    int wid = tid >> 5, lane = tid & 31;
    int bh = blockIdx.y;
    int b = bh / H_, h = bh % H_;
    int kvh = h / GROUPS_;
    int q0 = blockIdx.x * 128;

    // Q tile (grouped with first KV commit)
#pragma unroll
    for (int j = 0; j < 8; j++) {
        int idx = tid + j * 256;
        int r = idx >> 4, c = idx & 15;
        int pc = (c & 8) | ((c ^ r) & 7);
        cp16(Qs + r * 128 + (pc << 3),
             q + (((size_t)(b * T_ + q0 + r)) * H_ + h) * D_ + (c << 3));
    }
    {
        __half* Ks = KV;
        __half* Vs = KV + 64 * 128;
#pragma unroll
        for (int j = 0; j < 4; j++) {
            int idx = tid + j * 256;
            int r = idx >> 4, c = idx & 15;
            int pc = (c & 8) | ((c ^ r) & 7);
            size_t gofs = (((size_t)(b * T_ + r)) * KV_ + kvh) * D_ + (c << 3);
            cp16(Ks + r * 128 + (pc << 3), k + gofs);
            cp16(Vs + r * 128 + (pc << 3), v + gofs);
        }
        cp_commit();
    }

    float m0 = -1e30f, m1 = -1e30f, l0 = 0.f, l1 = 0.f;
    float oacc[16][4];
#pragma unroll
    for (int i = 0; i < 16; i++)
#pragma unroll
        for (int t = 0; t < 4; t++) oacc[i][t] = 0.f;

    const int nTile = T_ / 64;
    for (int it = 0; it < nTile; it++) {
        cp_wait_all();
        __syncthreads();
        if (it + 1 < nTile) {
            __half* Ks = KV + ((it + 1) & 1) * KVSTG;
            __half* Vs = Ks + 64 * 128;
            int nkv0 = (it + 1) * 64;
#pragma unroll
            for (int j = 0; j < 4; j++) {
                int idx = tid + j * 256;
                int r = idx >> 4, c = idx & 15;
                int pc = (c & 8) | ((c ^ r) & 7);
                size_t gofs = (((size_t)(b * T_ + nkv0 + r)) * KV_ + kvh) * D_ + (c << 3);
                cp16(Ks + r * 128 + (pc << 3), k + gofs);
                cp16(Vs + r * 128 + (pc << 3), v + gofs);
            }
            cp_commit();
        }
        const __half* Ks = KV + (it & 1) * KVSTG;
        const __half* Vs = Ks + 64 * 128;
        int kv0 = it * 64;

        // ---- S = Q @ K^T : 8 n8-tiles, 8 k16-steps over D ----
        float s[8][4];
#pragma unroll
        for (int i = 0; i < 8; i++)
#pragma unroll
            for (int t = 0; t < 4; t++) s[i][t] = 0.f;

#pragma unroll
        for (int ks = 0; ks < 8; ks++) {
            unsigned aq[4];
            int mm = lane >> 3;
            int r = wid * 16 + ((mm & 1) << 3) + (lane & 7);
            int c = (ks << 1) + (mm >> 1);
            int pc = (c & 8) | ((c ^ r) & 7);
            ldsm4(aq, smem_u32(Qs + r * 128 + (pc << 3)));
#pragma unroll
            for (int nt = 0; nt < 8; nt++) {
                unsigned bk[2];
                int kr = (nt << 3) + (lane & 7);
                int cc = (ks << 1) + ((lane >> 3) & 1);
                int pcc = (cc & 8) | ((cc ^ kr) & 7);
                ldsm2(bk, smem_u32(Ks + kr * 128 + (pcc << 3)));
                mma16816(s[nt], aq, bk);
            }
        }

        // ---- scale + {0,1} bias, online softmax (rows r0, r0+8) ----
        int r0 = q0 + wid * 16 + (lane >> 2);
        int r1 = r0 + 8;
        float ml0 = -1e30f, ml1 = -1e30f;
#pragma unroll
        for (int nt = 0; nt < 8; nt++) {
            int cb = kv0 + (nt << 3) + ((lane & 3) << 1);
            float b00 = ((cb     < LP_) || (r0 >= LP_ && cb     <= r0)) ? 1.f : 0.f;
            float b01 = ((cb + 1 < LP_) || (r0 >= LP_ && cb + 1 <= r0)) ? 1.f : 0.f;
            float b10 = ((cb     < LP_) || (r1 >= LP_ && cb     <= r1)) ? 1.f : 0.f;
            float b11 = ((cb + 1 < LP_) || (r1 >= LP_ && cb + 1 <= r1)) ? 1.f : 0.f;
            s[nt][0] = s[nt][0] * SCALE_ + b00;
            s[nt][1] = s[nt][1] * SCALE_ + b01;
            s[nt][2] = s[nt][2] * SCALE_ + b10;
            s[nt][3] = s[nt][3] * SCALE_ + b11;
            ml0 = fmaxf(ml0, fmaxf(s[nt][0], s[nt][1]));
            ml1 = fmaxf(ml1, fmaxf(s[nt][2], s[nt][3]));
        }
        ml0 = fmaxf(ml0, __shfl_xor_sync(0xffffffffu, ml0, 1));
        ml0 = fmaxf(ml0, __shfl_xor_sync(0xffffffffu, ml0, 2));
        ml1 = fmaxf(ml1, __shfl_xor_sync(0xffffffffu, ml1, 1));
        ml1 = fmaxf(ml1, __shfl_xor_sync(0xffffffffu, ml1, 2));
        float mn0 = fmaxf(m0, ml0), mn1 = fmaxf(m1, ml1);
        float al0 = __expf(m0 - mn0), al1 = __expf(m1 - mn1);
        m0 = mn0; m1 = mn1;
        float ls0 = 0.f, ls1 = 0.f;
#pragma unroll
        for (int nt = 0; nt < 8; nt++) {
            s[nt][0] = __expf(s[nt][0] - m0);
            s[nt][1] = __expf(s[nt][1] - m0);
            s[nt][2] = __expf(s[nt][2] - m1);
            s[nt][3] = __expf(s[nt][3] - m1);
            ls0 += s[nt][0] + s[nt][1];
            ls1 += s[nt][2] + s[nt][3];
        }
        ls0 += __shfl_xor_sync(0xffffffffu, ls0, 1);
        ls0 += __shfl_xor_sync(0xffffffffu, ls0, 2);
        ls1 += __shfl_xor_sync(0xffffffffu, ls1, 1);
        ls1 += __shfl_xor_sync(0xffffffffu, ls1, 2);
        l0 = l0 * al0 + ls0;
        l1 = l1 * al1 + ls1;
#pragma unroll
        for (int nt = 0; nt < 16; nt++) {
            oacc[nt][0] *= al0; oacc[nt][1] *= al0;
            oacc[nt][2] *= al1; oacc[nt][3] *= al1;
        }

        // ---- O += P @ V (P stays in registers as A-fragments) ----
#pragma unroll
        for (int kt = 0; kt < 4; kt++) {
            unsigned ap[4];
            ap[0] = pack_h2(s[2 * kt][0],     s[2 * kt][1]);
            ap[1] = pack_h2(s[2 * kt][2],     s[2 * kt][3]);
            ap[2] = pack_h2(s[2 * kt + 1][0], s[2 * kt + 1][1]);
            ap[3] = pack_h2(s[2 * kt + 1][2], s[2 * kt + 1][3]);
#pragma unroll
            for (int nt = 0; nt < 16; nt++) {
                unsigned bv[2];
                int kr = (kt << 4) + (lane & 15);
                int pc = (nt & 8) | ((nt ^ kr) & 7);
                ldsm2t(bv, smem_u32(Vs + kr * 128 + (pc << 3)));
                mma16816(oacc[nt], ap, bv);
            }
        }
    }

    // ---- normalize + write half to [B,T,H*D] ----
    float inv0 = 1.f / l0, inv1 = 1.f / l1;
    int r0 = q0 + wid * 16 + (lane >> 2);
    size_t ob0 = (((size_t)(b * T_ + r0)) * H_ + h) * D_;
    size_t ob1 = (((size_t)(b * T_ + r0 + 8)) * H_ + h) * D_;
#pragma unroll
    for (int nt = 0; nt < 16; nt++) {
        int c = (nt << 3) + ((lane & 3) << 1);
        *(__half2*)(o + ob0 + c) = __floats2half2_rn(oacc[nt][0] * inv0, oacc[nt][1] * inv0);
        *(__half2*)(o + ob1 + c) = __floats2half2_rn(oacc[nt][2] * inv1, oacc[nt][3] * inv1);
    }
}

// ---------------------------------------------------------------------------
extern "C" void kernel_launch(void* const* d_in, const int* in_sizes, int n_in,
                              void* d_out, int out_size)
{
    const float* hs = (const float*)d_in[0];
    const float* cs = (const float*)d_in[1];
    const float* sn = (const float*)d_in[2];
    const float* Wq = (const float*)d_in[3];
    const float* bq = (const float*)d_in[4];
    const float* Wk = (const float*)d_in[5];
    const float* bk = (const float*)d_in[6];
    const float* Wv = (const float*)d_in[7];
    const float* bv = (const float*)d_in[8];
    const float* Wo = (const float*)d_in[9];
    float* out = (float*)d_out;

    __half *hsh, *wqh, *wkh, *wvh, *woh, *qh, *kh, *vh, *aoh;
    cudaGetSymbolAddress((void**)&hsh, g_hsh);
    cudaGetSymbolAddress((void**)&wqh, g_wqh);
    cudaGetSymbolAddress((void**)&wkh, g_wkh);
    cudaGetSymbolAddress((void**)&wvh, g_wvh);
    cudaGetSymbolAddress((void**)&woh, g_woh);
    cudaGetSymbolAddress((void**)&qh, g_qh);
    cudaGetSymbolAddress((void**)&kh, g_kh);
    cudaGetSymbolAddress((void**)&vh, g_vh);
    cudaGetSymbolAddress((void**)&aoh, g_aoh);

    const int GEMM_SMEM = (128 * 64 + 64 * 128) * 2 * (int)sizeof(__half);   // 65536
    const int FLASH_SMEM = (128 * 128 + 2 * 2 * 64 * 128) * (int)sizeof(__half); // 98304
    cudaFuncSetAttribute(hgemm<1>, cudaFuncAttributeMaxDynamicSharedMemorySize, GEMM_SMEM);
    cudaFuncSetAttribute(hgemm<0>, cudaFuncAttributeMaxDynamicSharedMemorySize, GEMM_SMEM);
    cudaFuncSetAttribute(flash_h, cudaFuncAttributeMaxDynamicSharedMemorySize, FLASH_SMEM);

    const int M = MTOT_;

    // fp32 -> fp16 conversions
    {
        int n4;
        n4 = (M * C_) / 4;            f2h_kernel<<<(n4 + 255) / 256, 256>>>(hs, hsh, n4);
        n4 = (C_ * H_ * D_) / 4;      f2h_kernel<<<(n4 + 255) / 256, 256>>>(Wq, wqh, n4);
        n4 = (C_ * KV_ * D_) / 4;     f2h_kernel<<<(n4 + 255) / 256, 256>>>(Wk, wkh, n4);
        n4 = (C_ * KV_ * D_) / 4;     f2h_kernel<<<(n4 + 255) / 256, 256>>>(Wv, wvh, n4);
        n4 = (H_ * D_ * C_) / 4;      f2h_kernel<<<(n4 + 255) / 256, 256>>>(Wo, woh, n4);
    }

    // QKV projections (fp16 HMMA, half output)
    hgemm<1><<<dim3((H_ * D_) / 128, M / 128), 256, GEMM_SMEM>>>(M, H_ * D_, C_, hsh, wqh, bq, qh);
    hgemm<1><<<dim3((KV_ * D_) / 128, M / 128), 256, GEMM_SMEM>>>(M, KV_ * D_, C_, hsh, wkh, bk, kh);
    hgemm<1><<<dim3((KV_ * D_) / 128, M / 128), 256, GEMM_SMEM>>>(M, KV_ * D_, C_, hsh, wvh, bv, vh);

    // RoPE on q, k (positions >= LP), in place on half
    {
        int totq = B_ * L_ * H_ * 64;
        rope_h<<<(totq + 255) / 256, 256>>>(qh, cs, sn, H_);
        int totk = B_ * L_ * KV_ * 64;
        rope_h<<<(totk + 255) / 256, 256>>>(kh, cs, sn, KV_);
    }

    // Attention (HMMA flash), writes half directly
    flash_h<<<dim3(T_ / 128, B_ * H_), 256, FLASH_SMEM>>>(qh, kh, vh, aoh);

    // Output projection (fp32 output)
    hgemm<0><<<dim3(C_ / 128, M / 128), 256, GEMM_SMEM>>>(M, C_, H_ * D_, aoh, woh, nullptr, out);
}

// round 8
// speedup vs baseline: 7.2231x; 1.1950x over previous
#include <cuda_runtime.h>
#include <cuda_fp16.h>

// Problem constants
#define B_ 2
#define T_ 2048
#define C_ 2048
#define H_ 16
#define KV_ 4
#define D_ 128
#define LP_ 64
#define L_ (T_ - LP_)
#define GROUPS_ (H_ / KV_)
#define SCALE_ 0.08838834764831845f   // 128^-0.5
#define LOG2E_ 1.4426950408889634f
#define MTOT_ (B_ * T_)
#define NQKV_ 3072                    // H*D + 2*KV*D
#define QKVS_ 3072                    // row stride of fused qkv output

// ---------------- scratch (no runtime allocation allowed) -------------------
__device__ __half g_hsh [(size_t)MTOT_ * C_];        // hidden_states fp16
__device__ __half g_wqkv[(size_t)C_ * NQKV_];        // packed [Wq|Wk|Wv] fp16
__device__ float  g_bqkv[NQKV_];                     // packed bias
__device__ __half g_woh [(size_t)H_ * D_ * C_];
__device__ __half g_qkvh[(size_t)MTOT_ * NQKV_];     // fused QKV output
__device__ __half g_aoh [(size_t)MTOT_ * H_ * D_];   // attention out fp16

// ---------------- PTX helpers ----------------------------------------------
__device__ __forceinline__ unsigned smem_u32(const void* p) {
    return (unsigned)__cvta_generic_to_shared(p);
}
__device__ __forceinline__ void cp16(void* dst, const void* src) {
    asm volatile("cp.async.cg.shared.global [%0], [%1], 16;"
                 :: "r"(smem_u32(dst)), "l"(src));
}
__device__ __forceinline__ void cp_commit() { asm volatile("cp.async.commit_group;"); }
__device__ __forceinline__ void cp_wait_all() { asm volatile("cp.async.wait_group 0;"); }
__device__ __forceinline__ void cp_wait1()    { asm volatile("cp.async.wait_group 1;"); }

__device__ __forceinline__ void ldsm4(unsigned* a, unsigned addr) {
    asm volatile("ldmatrix.sync.aligned.m8n8.x4.shared.b16 {%0,%1,%2,%3}, [%4];"
                 : "=r"(a[0]), "=r"(a[1]), "=r"(a[2]), "=r"(a[3]) : "r"(addr));
}
__device__ __forceinline__ void ldsm4t(unsigned* a, unsigned addr) {
    asm volatile("ldmatrix.sync.aligned.m8n8.x4.trans.shared.b16 {%0,%1,%2,%3}, [%4];"
                 : "=r"(a[0]), "=r"(a[1]), "=r"(a[2]), "=r"(a[3]) : "r"(addr));
}
__device__ __forceinline__ void mma16816(float* c, const unsigned* a, const unsigned* b) {
    asm volatile(
        "mma.sync.aligned.m16n8k16.row.col.f32.f16.f16.f32 "
        "{%0,%1,%2,%3},{%4,%5,%6,%7},{%8,%9},{%0,%1,%2,%3};"
        : "+f"(c[0]), "+f"(c[1]), "+f"(c[2]), "+f"(c[3])
        : "r"(a[0]), "r"(a[1]), "r"(a[2]), "r"(a[3]), "r"(b[0]), "r"(b[1]));
}
__device__ __forceinline__ unsigned pack_h2(float a, float b) {
    __half2 h = __floats2half2_rn(a, b);
    return *reinterpret_cast<unsigned*>(&h);
}
__device__ __forceinline__ float ex2f(float x) {
    float y;
    asm("ex2.approx.f32 %0, %1;" : "=f"(y) : "f"(x));
    return y;
}

// ---------------- conversions / packing -------------------------------------
__global__ void f2h_kernel(const float* __restrict__ x, __half* __restrict__ y, int n4) {
    int i = blockIdx.x * blockDim.x + threadIdx.x;
    if (i >= n4) return;
    float4 v = ((const float4*)x)[i];
    ((__half2*)y)[i * 2 + 0] = __floats2half2_rn(v.x, v.y);
    ((__half2*)y)[i * 2 + 1] = __floats2half2_rn(v.z, v.w);
}

__global__ void pack_qkv_w(const float* __restrict__ Wq, const float* __restrict__ Wk,
                           const float* __restrict__ Wv, __half* __restrict__ dst) {
    int i = blockIdx.x * blockDim.x + threadIdx.x;
    const int n4 = C_ * NQKV_ / 4;
    if (i >= n4) return;
    int row = i / (NQKV_ / 4);
    int c4 = i - row * (NQKV_ / 4);
    const float* src;
    int col;
    if (c4 < 512)      { src = Wq + (size_t)row * (H_ * D_);  col = c4 * 4; }
    else if (c4 < 640) { src = Wk + (size_t)row * (KV_ * D_); col = (c4 - 512) * 4; }
    else               { src = Wv + (size_t)row * (KV_ * D_); col = (c4 - 640) * 4; }
    float4 v = *(const float4*)(src + col);
    __half2* d = (__half2*)(dst + (size_t)row * NQKV_ + c4 * 4);
    d[0] = __floats2half2_rn(v.x, v.y);
    d[1] = __floats2half2_rn(v.z, v.w);
}

__global__ void pack_qkv_b(const float* __restrict__ bq, const float* __restrict__ bk,
                           const float* __restrict__ bv, float* __restrict__ dst) {
    int c = blockIdx.x * blockDim.x + threadIdx.x;
    if (c >= NQKV_) return;
    dst[c] = c < 2048 ? bq[c] : (c < 2560 ? bk[c - 2048] : bv[c - 2560]);
}

// ---------------- RoPE in place on half (row stride QKVS_) -------------------
__global__ void rope_h(__half* __restrict__ x, const float* __restrict__ cs,
                       const float* __restrict__ sn, int NH) {
    int idx = blockIdx.x * blockDim.x + threadIdx.x;
    int total = B_ * L_ * NH * 64;
    if (idx >= total) return;
    int d = idx & 63;
    int h = (idx >> 6) % NH;
    int tt = (idx / (64 * NH)) % L_;
    int b = idx / (64 * NH * L_);
    size_t base = ((size_t)(b * T_ + LP_ + tt)) * QKVS_ + h * D_;
    size_t cb = ((size_t)b * L_ + tt) * D_;
    float x0 = __half2float(x[base + d]), x1 = __half2float(x[base + d + 64]);
    float c0 = cs[cb + d], c1 = cs[cb + d + 64];
    float s0 = sn[cb + d], s1 = sn[cb + d + 64];
    x[base + d]      = __float2half_rn(x0 * c0 - x1 * s0);
    x[base + d + 64] = __float2half_rn(x1 * c1 + x0 * s1);
}

// ---------------- fp16 tensor-core GEMM --------------------------------------
// C[M,N] = A[M,K] @ B[K,N] (+bias). 128x128x64 tile, 8 warps (64x32 each),
// 3-stage cp.async ring (wait_group 1), XOR-swizzled smem, ldmatrix + mma.
__device__ __forceinline__ void gemm_load_tile(
    __half* As_, __half* Bs_, const __half* __restrict__ A, const __half* __restrict__ B,
    int row0, int col0, int k0, int K, int N, int tid)
{
#pragma unroll
    for (int j = 0; j < 4; j++) {             // A: 128x64 halves = 1024 x 16B
        int idx = tid + j * 256;
        int ar = idx >> 3, ac = idx & 7;
        cp16(As_ + ar * 64 + ((ac ^ (ar & 7)) << 3),
             A + (size_t)(row0 + ar) * K + k0 + (ac << 3));
    }
#pragma unroll
    for (int j = 0; j < 4; j++) {             // B: 64x128 halves
        int idx = tid + j * 256;
        int br = idx >> 4, bc = idx & 15;
        int pc = (bc & 8) | ((bc ^ br) & 7);
        cp16(Bs_ + br * 128 + (pc << 3),
             B + (size_t)(k0 + br) * N + col0 + (bc << 3));
    }
    cp_commit();
}

template <int OUT_HALF>
__global__ __launch_bounds__(256, 2) void hgemm(
    int M, int N, int K,
    const __half* __restrict__ A, const __half* __restrict__ B,
    const float* __restrict__ bias, void* __restrict__ Cout)
{
    extern __shared__ __half sgm[];
    const int STG = 128 * 64 + 64 * 128;      // halves per stage
    int tid = threadIdx.x;
    int wid = tid >> 5, lane = tid & 31;
    int wm = wid & 1, wn = wid >> 1;
    int row0 = blockIdx.y * 128, col0 = blockIdx.x * 128;

    float acc[4][4][4];
#pragma unroll
    for (int i = 0; i < 4; i++)
#pragma unroll
        for (int j = 0; j < 4; j++)
#pragma unroll
            for (int t = 0; t < 4; t++) acc[i][j][t] = 0.f;

    const int nIter = K / 64;                  // >= 2 for all calls here
    gemm_load_tile(sgm + 0 * STG, sgm + 0 * STG + 128 * 64, A, B, row0, col0, 0, K, N, tid);
    gemm_load_tile(sgm + 1 * STG, sgm + 1 * STG + 128 * 64, A, B, row0, col0, 64, K, N, tid);

    for (int it = 0; it < nIter; it++) {
        cp_wait1();
        __syncthreads();
        if (it + 2 < nIter) {
            __half* As_ = sgm + ((it + 2) % 3) * STG;
            gemm_load_tile(As_, As_ + 128 * 64, A, B, row0, col0, (it + 2) * 64, K, N, tid);
        } else {
            cp_commit();                       // keep group accounting aligned
        }
        const __half* As = sgm + (it % 3) * STG;
        const __half* Bs = As + 128 * 64;
#pragma unroll
        for (int ks = 0; ks < 4; ks++) {
            unsigned af[4][4];
#pragma unroll
            for (int mt = 0; mt < 4; mt++) {
                int mm = lane >> 3;
                int r = wm * 64 + mt * 16 + ((mm & 1) << 3) + (lane & 7);
                int c = (ks << 1) + (mm >> 1);
                ldsm4(af[mt], smem_u32(As + r * 64 + (((c ^ r) & 7) << 3)));
            }
#pragma unroll
            for (int ntp = 0; ntp < 2; ntp++) {
                unsigned bf[4];
                int csel = (wn << 2) + (ntp << 1) + (lane >> 4);
                int kr = (ks << 4) + (lane & 15);
                int pc = (csel & 8) | ((csel ^ kr) & 7);
                ldsm4t(bf, smem_u32(Bs + kr * 128 + (pc << 3)));
#pragma unroll
                for (int mt = 0; mt < 4; mt++) {
                    mma16816(acc[mt][2 * ntp],     af[mt], bf);
                    mma16816(acc[mt][2 * ntp + 1], af[mt], bf + 2);
                }
            }
        }
    }

#pragma unroll
    for (int mt = 0; mt < 4; mt++)
#pragma unroll
        for (int nt = 0; nt < 4; nt++) {
            int r = row0 + wm * 64 + mt * 16 + (lane >> 2);
            int c = col0 + (wn << 5) + (nt << 3) + ((lane & 3) << 1);
            float b0 = bias ? bias[c] : 0.f;
            float b1 = bias ? bias[c + 1] : 0.f;
            if (OUT_HALF) {
                __half* O = (__half*)Cout;
                *(__half2*)(O + (size_t)r * N + c) =
                    __floats2half2_rn(acc[mt][nt][0] + b0, acc[mt][nt][1] + b1);
                *(__half2*)(O + (size_t)(r + 8) * N + c) =
                    __floats2half2_rn(acc[mt][nt][2] + b0, acc[mt][nt][3] + b1);
            } else {
                float* O = (float*)Cout;
                *(float2*)(O + (size_t)r * N + c) =
                    make_float2(acc[mt][nt][0] + b0, acc[mt][nt][1] + b1);
                *(float2*)(O + (size_t)(r + 8) * N + c) =
                    make_float2(acc[mt][nt][2] + b0, acc[mt][nt][3] + b1);
            }
        }
}

// ---------------- fp16 flash attention ---------------------------------------
// BQ=128 (16 rows/warp), BKV=64, D=128. q/k/v live in the fused QKV buffer
// (row stride QKVS_). Additive {0,1} bias folded in log2-domain softmax.
__global__ __launch_bounds__(256, 2) void flash_h(
    const __half* __restrict__ q, const __half* __restrict__ k,
    const __half* __restrict__ v, __half* __restrict__ o)
{
    extern __shared__ __half sgm[];
    __half* Qs = sgm;                       // [128][128] swizzled
    __half* KV = sgm + 128 * 128;           // 2 stages x {K[64][128], V[64][128]}
    const int KVSTG = 2 * 64 * 128;

    int tid = threadIdx.x;
    int wid = tid >> 5, lane = tid & 31;
    int bh = blockIdx.y;
    int b = bh / H_, h = bh % H_;
    int kvh = h / GROUPS_;
    int q0 = blockIdx.x * 128;

    // Q tile (grouped with first KV commit)
#pragma unroll
    for (int j = 0; j < 8; j++) {
        int idx = tid + j * 256;
        int r = idx >> 4, c = idx & 15;
        int pc = (c & 8) | ((c ^ r) & 7);
        cp16(Qs + r * 128 + (pc << 3),
             q + ((size_t)(b * T_ + q0 + r)) * QKVS_ + h * D_ + (c << 3));
    }
    {
        __half* Ks = KV;
        __half* Vs = KV + 64 * 128;
#pragma unroll
        for (int j = 0; j < 4; j++) {
            int idx = tid + j * 256;
            int r = idx >> 4, c = idx & 15;
            int pc = (c & 8) | ((c ^ r) & 7);
            size_t gofs = ((size_t)(b * T_ + r)) * QKVS_ + kvh * D_ + (c << 3);
            cp16(Ks + r * 128 + (pc << 3), k + gofs);
            cp16(Vs + r * 128 + (pc << 3), v + gofs);
        }
        cp_commit();
    }

    float m0 = -1e30f, m1 = -1e30f, l0 = 0.f, l1 = 0.f;
    float oacc[16][4];
#pragma unroll
    for (int i = 0; i < 16; i++)
#pragma unroll
        for (int t = 0; t < 4; t++) oacc[i][t] = 0.f;

    const float SC2 = SCALE_ * LOG2E_;
    const int nTile = T_ / 64;
    for (int it = 0; it < nTile; it++) {
        cp_wait_all();
        __syncthreads();
        if (it + 1 < nTile) {
            __half* Ks = KV + ((it + 1) & 1) * KVSTG;
            __half* Vs = Ks + 64 * 128;
            int nkv0 = (it + 1) * 64;
#pragma unroll
            for (int j = 0; j < 4; j++) {
                int idx = tid + j * 256;
                int r = idx >> 4, c = idx & 15;
                int pc = (c & 8) | ((c ^ r) & 7);
                size_t gofs = ((size_t)(b * T_ + nkv0 + r)) * QKVS_ + kvh * D_ + (c << 3);
                cp16(Ks + r * 128 + (pc << 3), k + gofs);
                cp16(Vs + r * 128 + (pc << 3), v + gofs);
            }
            cp_commit();
        }
        const __half* Ks = KV + (it & 1) * KVSTG;
        const __half* Vs = Ks + 64 * 128;
        int kv0 = it * 64;

        // ---- S = Q @ K^T : 8 n8-tiles (merged in pairs), 8 k16-steps ----
        float s[8][4];
#pragma unroll
        for (int i = 0; i < 8; i++)
#pragma unroll
            for (int t = 0; t < 4; t++) s[i][t] = 0.f;

#pragma unroll
        for (int ks = 0; ks < 8; ks++) {
            unsigned aq[4];
            int mm = lane >> 3;
            int r = wid * 16 + ((mm & 1) << 3) + (lane & 7);
            int c = (ks << 1) + (mm >> 1);
            int pc = (c & 8) | ((c ^ r) & 7);
            ldsm4(aq, smem_u32(Qs + r * 128 + (pc << 3)));
#pragma unroll
            for (int ntp = 0; ntp < 4; ntp++) {
                unsigned bk4[4];
                int ntsel = (ntp << 1) + (lane >> 4);
                int kr = (ntsel << 3) + (lane & 7);
                int cc = (ks << 1) + ((lane >> 3) & 1);
                int pcc = (cc & 8) | ((cc ^ kr) & 7);
                ldsm4(bk4, smem_u32(Ks + kr * 128 + (pcc << 3)));
                mma16816(s[2 * ntp],     aq, bk4);
                mma16816(s[2 * ntp + 1], aq, bk4 + 2);
            }
        }

        // ---- scale + {0,1} bias in log2 domain, online softmax ----
        int r0 = q0 + wid * 16 + (lane >> 2);
        int r1 = r0 + 8;
        float ml0 = -1e30f, ml1 = -1e30f;
#pragma unroll
        for (int nt = 0; nt < 8; nt++) {
            int cb = kv0 + (nt << 3) + ((lane & 3) << 1);
            float b00 = ((cb     < LP_) || (r0 >= LP_ && cb     <= r0)) ? LOG2E_ : 0.f;
            float b01 = ((cb + 1 < LP_) || (r0 >= LP_ && cb + 1 <= r0)) ? LOG2E_ : 0.f;
            float b10 = ((cb     < LP_) || (r1 >= LP_ && cb     <= r1)) ? LOG2E_ : 0.f;
            float b11 = ((cb + 1 < LP_) || (r1 >= LP_ && cb + 1 <= r1)) ? LOG2E_ : 0.f;
            s[nt][0] = s[nt][0] * SC2 + b00;
            s[nt][1] = s[nt][1] * SC2 + b01;
            s[nt][2] = s[nt][2] * SC2 + b10;
            s[nt][3] = s[nt][3] * SC2 + b11;
            ml0 = fmaxf(ml0, fmaxf(s[nt][0], s[nt][1]));
            ml1 = fmaxf(ml1, fmaxf(s[nt][2], s[nt][3]));
        }
        ml0 = fmaxf(ml0, __shfl_xor_sync(0xffffffffu, ml0, 1));
        ml0 = fmaxf(ml0, __shfl_xor_sync(0xffffffffu, ml0, 2));
        ml1 = fmaxf(ml1, __shfl_xor_sync(0xffffffffu, ml1, 1));
        ml1 = fmaxf(ml1, __shfl_xor_sync(0xffffffffu, ml1, 2));
        float mn0 = fmaxf(m0, ml0), mn1 = fmaxf(m1, ml1);
        float al0 = ex2f(m0 - mn0), al1 = ex2f(m1 - mn1);
        m0 = mn0; m1 = mn1;
        float ls0 = 0.f, ls1 = 0.f;
#pragma unroll
        for (int nt = 0; nt < 8; nt++) {
            s[nt][0] = ex2f(s[nt][0] - m0);
            s[nt][1] = ex2f(s[nt][1] - m0);
            s[nt][2] = ex2f(s[nt][2] - m1);
            s[nt][3] = ex2f(s[nt][3] - m1);
            ls0 += s[nt][0] + s[nt][1];
            ls1 += s[nt][2] + s[nt][3];
        }
        ls0 += __shfl_xor_sync(0xffffffffu, ls0, 1);
        ls0 += __shfl_xor_sync(0xffffffffu, ls0, 2);
        ls1 += __shfl_xor_sync(0xffffffffu, ls1, 1);
        ls1 += __shfl_xor_sync(0xffffffffu, ls1, 2);
        l0 = l0 * al0 + ls0;
        l1 = l1 * al1 + ls1;
#pragma unroll
        for (int nt = 0; nt < 16; nt++) {
            oacc[nt][0] *= al0; oacc[nt][1] *= al0;
            oacc[nt][2] *= al1; oacc[nt][3] *= al1;
        }

        // ---- O += P @ V (P in registers, V via merged ldsm4t) ----
#pragma unroll
        for (int kt = 0; kt < 4; kt++) {
            unsigned ap[4];
            ap[0] = pack_h2(s[2 * kt][0],     s[2 * kt][1]);
            ap[1] = pack_h2(s[2 * kt][2],     s[2 * kt][3]);
            ap[2] = pack_h2(s[2 * kt + 1][0], s[2 * kt + 1][1]);
            ap[3] = pack_h2(s[2 * kt + 1][2], s[2 * kt + 1][3]);
#pragma unroll
            for (int ntp = 0; ntp < 8; ntp++) {
                unsigned bv4[4];
                int ntsel = (ntp << 1) + (lane >> 4);
                int kr = (kt << 4) + (lane & 15);
                int pc = (ntsel & 8) | ((ntsel ^ kr) & 7);
                ldsm4t(bv4, smem_u32(Vs + kr * 128 + (pc << 3)));
                mma16816(oacc[2 * ntp],     ap, bv4);
                mma16816(oacc[2 * ntp + 1], ap, bv4 + 2);
            }
        }
    }

    // ---- normalize + write half to [B,T,H*D] ----
    float inv0 = 1.f / l0, inv1 = 1.f / l1;
    int r0 = q0 + wid * 16 + (lane >> 2);
    size_t ob0 = (((size_t)(b * T_ + r0)) * H_ + h) * D_;
    size_t ob1 = (((size_t)(b * T_ + r0 + 8)) * H_ + h) * D_;
#pragma unroll
    for (int nt = 0; nt < 16; nt++) {
        int c = (nt << 3) + ((lane & 3) << 1);
        *(__half2*)(o + ob0 + c) = __floats2half2_rn(oacc[nt][0] * inv0, oacc[nt][1] * inv0);
        *(__half2*)(o + ob1 + c) = __floats2half2_rn(oacc[nt][2] * inv1, oacc[nt][3] * inv1);
    }
}

// ---------------------------------------------------------------------------
extern "C" void kernel_launch(void* const* d_in, const int* in_sizes, int n_in,
                              void* d_out, int out_size)
{
    const float* hs = (const float*)d_in[0];
    const float* cs = (const float*)d_in[1];
    const float* sn = (const float*)d_in[2];
    const float* Wq = (const float*)d_in[3];
    const float* bq = (const float*)d_in[4];
    const float* Wk = (const float*)d_in[5];
    const float* bk = (const float*)d_in[6];
    const float* Wv = (const float*)d_in[7];
    const float* bv = (const float*)d_in[8];
    const float* Wo = (const float*)d_in[9];
    float* out = (float*)d_out;

    __half *hsh, *wqkv, *woh, *qkvh, *aoh;
    float* bqkv;
    cudaGetSymbolAddress((void**)&hsh, g_hsh);
    cudaGetSymbolAddress((void**)&wqkv, g_wqkv);
    cudaGetSymbolAddress((void**)&bqkv, g_bqkv);
    cudaGetSymbolAddress((void**)&woh, g_woh);
    cudaGetSymbolAddress((void**)&qkvh, g_qkvh);
    cudaGetSymbolAddress((void**)&aoh, g_aoh);

    const int GEMM_SMEM = (128 * 64 + 64 * 128) * 3 * (int)sizeof(__half);        // 98304
    const int FLASH_SMEM = (128 * 128 + 2 * 2 * 64 * 128) * (int)sizeof(__half);  // 98304
    cudaFuncSetAttribute(hgemm<1>, cudaFuncAttributeMaxDynamicSharedMemorySize, GEMM_SMEM);
    cudaFuncSetAttribute(hgemm<0>, cudaFuncAttributeMaxDynamicSharedMemorySize, GEMM_SMEM);
    cudaFuncSetAttribute(flash_h, cudaFuncAttributeMaxDynamicSharedMemorySize, FLASH_SMEM);

    const int M = MTOT_;

    // fp32 -> fp16 conversions + weight/bias packing
    {
        int n4 = (M * C_) / 4;
        f2h_kernel<<<(n4 + 255) / 256, 256>>>(hs, hsh, n4);
        int nw = (C_ * NQKV_) / 4;
        pack_qkv_w<<<(nw + 255) / 256, 256>>>(Wq, Wk, Wv, wqkv);
        pack_qkv_b<<<(NQKV_ + 255) / 256, 256>>>(bq, bk, bv, bqkv);
        n4 = (H_ * D_ * C_) / 4;
        f2h_kernel<<<(n4 + 255) / 256, 256>>>(Wo, woh, n4);
    }

    // Fused QKV projection: [M, 3072] = hs @ [Wq|Wk|Wv] + bias
    hgemm<1><<<dim3(NQKV_ / 128, M / 128), 256, GEMM_SMEM>>>(M, NQKV_, C_, hsh, wqkv, bqkv, qkvh);

    // RoPE on q, k (positions >= LP), in place in the fused buffer
    {
        int totq = B_ * L_ * H_ * 64;
        rope_h<<<(totq + 255) / 256, 256>>>(qkvh, cs, sn, H_);
        int totk = B_ * L_ * KV_ * 64;
        rope_h<<<(totk + 255) / 256, 256>>>(qkvh + H_ * D_, cs, sn, KV_);
    }

    // Attention (HMMA flash) over the fused buffer
    flash_h<<<dim3(T_ / 128, B_ * H_), 256, FLASH_SMEM>>>(
        qkvh, qkvh + H_ * D_, qkvh + H_ * D_ + KV_ * D_, aoh);

    // Output projection (fp32 output)
    hgemm<0><<<dim3(C_ / 128, M / 128), 256, GEMM_SMEM>>>(M, C_, H_ * D_, aoh, woh, nullptr, out);
}